// round 10
// baseline (speedup 1.0000x reference)
#include <cuda_runtime.h>
#include <cuda_bf16.h>
#include <cstdint>

constexpr int Bb  = 64;
constexpr int BSs = 8;
constexpr int Mm  = 512;
constexpr int Dd  = 256;
constexpr float NEG_FILL_F = -10000000000.0f;

// bf16 fused path: chunk = 32 bf16 k; stage = 4 tiles (Ahi,Alo,Bhi,Blo) x 8KB
constexpr int DEPTH_BF = 3;
constexpr int TSZ     = 8192;                          // bytes per tile
constexpr int BSTAGE  = 4 * TSZ;                       // 32KB per stage
constexpr int DSMEM_BF = DEPTH_BF * BSTAGE;            // 98304 B (96KB)
// fp32 NN path (ctx): BK=16 fp32, DEPTH=4
constexpr int DEPTH_NN = 4;
constexpr int BK32   = 16;
constexpr int BNNP   = 136;
constexpr int ASTG32   = 128 * BK32;                   // floats
constexpr int BSTG_NN  = BK32 * BNNP;                  // floats
constexpr int DSMEM_NN = DEPTH_NN * (ASTG32 + BSTG_NN) * 4;  // 67584 B

// ---------------- scratch ------------------------------------------------------
__device__ __nv_bfloat16 g_x2[(size_t)Bb * Mm * 2 * Dd];   // [hi|lo] width 512
__device__ __nv_bfloat16 g_y2[(size_t)BSs * Mm * 2 * Dd];
__device__ __nv_bfloat16 g_W2[3][(size_t)Dd * 2 * Dd];
__device__ __nv_bfloat16 g_Qx2[(size_t)Bb * Mm * 2 * Dd];
__device__ __nv_bfloat16 g_Kx2[(size_t)Bb * Mm * 2 * Dd];
__device__ __nv_bfloat16 g_Qy2[(size_t)BSs * Mm * 2 * Dd];
__device__ __nv_bfloat16 g_Ky2[(size_t)BSs * Mm * 2 * Dd];
__device__ float g_Vx[(size_t)Bb * Mm * Dd];        // V fp32 tf32-rna
__device__ float g_Vy[(size_t)BSs * Mm * Dd];
__device__ float g_Px[(size_t)Bb * Mm * Mm];        // probs tf32-rna, sp-permuted
__device__ float g_Py[(size_t)BSs * Mm * Mm];
__device__ unsigned char g_mx[Bb * Mm];
__device__ unsigned char g_my[BSs * Mm];

// ---------------- helpers ------------------------------------------------------
__device__ __forceinline__ int sp(int k) {          // involution, used for P only
    return (k & ~15) | ((k & 3) << 2) | ((k >> 2) & 3);
}
__device__ __forceinline__ float tf32_rna(float a) {
    uint32_t o;
    asm("cvt.rna.tf32.f32 %0, %1;" : "=r"(o) : "f"(a));
    return __uint_as_float(o);
}
__device__ __forceinline__ uint32_t smem_u32(const void* p) {
    uint32_t a;
    asm("{ .reg .u64 t; cvta.to.shared.u64 t, %1; cvt.u32.u64 %0, t; }"
        : "=r"(a) : "l"(p));
    return a;
}
__device__ __forceinline__ void cpa16(uint32_t dst, const void* src) {
    asm volatile("cp.async.cg.shared.global [%0], [%1], 16;"
                 :: "r"(dst), "l"(src) : "memory");
}
__device__ __forceinline__ void ldm_x4(uint32_t* r, uint32_t addr) {
    asm volatile("ldmatrix.sync.aligned.m8n8.x4.shared.b16 {%0,%1,%2,%3}, [%4];"
        : "=r"(r[0]), "=r"(r[1]), "=r"(r[2]), "=r"(r[3]) : "r"(addr));
}
__device__ __forceinline__ void mma_bf16(float* c, const uint32_t* a,
                                         uint32_t b0, uint32_t b1) {
    asm volatile(
        "mma.sync.aligned.m16n8k16.row.col.f32.bf16.bf16.f32 "
        "{%0,%1,%2,%3}, {%4,%5,%6,%7}, {%8,%9}, {%0,%1,%2,%3};"
        : "+f"(c[0]), "+f"(c[1]), "+f"(c[2]), "+f"(c[3])
        : "r"(a[0]), "r"(a[1]), "r"(a[2]), "r"(a[3]), "r"(b0), "r"(b1));
}
__device__ __forceinline__ void mma_tf32(float* c, const uint32_t* a, const uint32_t* b) {
    asm volatile(
        "mma.sync.aligned.m16n8k8.row.col.f32.tf32.tf32.f32 "
        "{%0,%1,%2,%3}, {%4,%5,%6,%7}, {%8,%9}, {%0,%1,%2,%3};"
        : "+f"(c[0]), "+f"(c[1]), "+f"(c[2]), "+f"(c[3])
        : "r"(a[0]), "r"(a[1]), "r"(a[2]), "r"(a[3]), "r"(b[0]), "r"(b[1]));
}

// ============================ fused bf16 NT GEMM path ==========================
// Per 32-k chunk, stage 4 tiles (Ahi,Alo,Bhi,Blo), each 128 rows x 64B.
// Slot swizzle (4 slots of 16B / row): phys_slot = g ^ ((row>>1)&3).
// One chunk issues all three product terms hi*hi + lo*hi + hi*lo.
__device__ __forceinline__ void issue_stage_f(
    const __nv_bfloat16* __restrict__ A, const __nv_bfloat16* __restrict__ B,
    int c, int nch, uint32_t sb)
{
    if (c < nch) {
        uint32_t sd = sb + (c % DEPTH_BF) * BSTAGE;
        int acol = c * 32;
#pragma unroll
        for (int j = 0; j < 2; j++) {
            int idx = threadIdx.x + 256 * j;
            int row = idx >> 2, slot = idx & 3;
            int g = slot ^ ((row >> 1) & 3);
            uint32_t so = row * 64 + slot * 16;
            const __nv_bfloat16* ap = A + (size_t)row * 512 + acol + g * 8;
            const __nv_bfloat16* bp = B + (size_t)row * 512 + acol + g * 8;
            cpa16(sd + so, ap);                       // A hi
            cpa16(sd + TSZ + so, ap + 256);           // A lo
            cpa16(sd + 2 * TSZ + so, bp);             // B hi
            cpa16(sd + 3 * TSZ + so, bp + 256);       // B lo
        }
    }
    asm volatile("cp.async.commit_group;" ::: "memory");
}

// warp tile 64(m) x 32(n); 8 warps 2x4 over 128x128 CTA tile; 32 k per chunk.
__device__ __forceinline__ void compute_chunk_f(
    uint32_t sd, float (&acc)[4][4][4], int wm, int wn, int lane)
{
    int j = lane >> 3, rin = lane & 7;
    int jk = j >> 1, jo = (j & 1) * 8;
    int rowA = wm * 64 + jo + rin;
    int rowB = wn * 32 + jo + rin;
    int swA = (rowA >> 1) & 3, swB = (rowB >> 1) & 3;
#pragma unroll
    for (int ks = 0; ks < 2; ks++) {
        uint32_t slA = (uint32_t)(((ks * 2 + jk) ^ swA) * 16);
        uint32_t slB = (uint32_t)(((ks * 2 + jk) ^ swB) * 16);
        uint32_t bhi[2][4], blo[2][4];
#pragma unroll
        for (int np = 0; np < 2; np++) {
            ldm_x4(bhi[np], sd + 2 * TSZ + (rowB + np * 16) * 64 + slB);
            ldm_x4(blo[np], sd + 3 * TSZ + (rowB + np * 16) * 64 + slB);
        }
#pragma unroll
        for (int mt = 0; mt < 4; mt++) {
            uint32_t ahi[4], alo[4];
            ldm_x4(ahi, sd + (rowA + mt * 16) * 64 + slA);
            ldm_x4(alo, sd + TSZ + (rowA + mt * 16) * 64 + slA);
#pragma unroll
            for (int nt = 0; nt < 4; nt++) {
                uint32_t b0 = bhi[nt >> 1][nt & 1], b1 = bhi[nt >> 1][(nt & 1) + 2];
                mma_bf16(acc[mt][nt], ahi, b0, b1);
                mma_bf16(acc[mt][nt], alo, b0, b1);
                mma_bf16(acc[mt][nt], ahi,
                         blo[nt >> 1][nt & 1], blo[nt >> 1][(nt & 1) + 2]);
            }
        }
    }
}

__device__ __forceinline__ void gemm_bf16(
    const __nv_bfloat16* __restrict__ A, const __nv_bfloat16* __restrict__ B,
    float (&acc)[4][4][4], uint32_t sb, int wm, int wn, int lane)
{
    constexpr int nch = 8;   // 8 chunks of 32 k over K=256, fused 3 terms
#pragma unroll
    for (int s = 0; s < DEPTH_BF - 1; s++)
        issue_stage_f(A, B, s, nch, sb);
    for (int c = 0; c < nch; c++) {
        asm volatile("cp.async.wait_group 1;" ::: "memory");
        __syncthreads();
        issue_stage_f(A, B, c + DEPTH_BF - 1, nch, sb);
        compute_chunk_f(sb + (c % DEPTH_BF) * BSTAGE, acc, wm, wn, lane);
    }
}

#define BF16_SETUP()                                        \
    extern __shared__ char smem[];                          \
    uint32_t sb = smem_u32(smem);                           \
    int wid = threadIdx.x >> 5, lane = threadIdx.x & 31;    \
    int wm = wid >> 2, wn = wid & 3;                        \
    int gr = lane >> 2, kc = lane & 3;                      \
    float acc[4][4][4];                                     \
    _Pragma("unroll") for (int i = 0; i < 4; i++)           \
    _Pragma("unroll") for (int jj = 0; jj < 4; jj++)        \
    _Pragma("unroll") for (int q = 0; q < 4; q++) acc[i][jj][q] = 0.f;

// ============================ fp32 NN path (ctx only) ==========================
__device__ __forceinline__ void issue_stage_nn(
    const float* __restrict__ A, int lda, const float* __restrict__ B, int ldb,
    int c, int nch, uint32_t asb, uint32_t bsb)
{
    if (c < nch) {
        int kc = c;
        int buf = c & (DEPTH_NN - 1);
        uint32_t ad = asb + buf * (ASTG32 * 4);
        uint32_t bd = bsb + buf * (BSTG_NN * 4);
#pragma unroll
        for (int j = 0; j < 2; j++) {             // A: 128 rows x 4 slots
            int idx = threadIdx.x + 256 * j;
            int row = idx >> 2, slot = idx & 3;
            int g = slot ^ (row & 3);
            cpa16(ad + row * 64 + slot * 16, A + (size_t)row * lda + kc * BK32 + g * 4);
        }
#pragma unroll
        for (int j = 0; j < 2; j++) {             // B: 16 k-rows x 32 segs
            int idx = threadIdx.x + 256 * j;
            int row = idx >> 5, seg = idx & 31;
            cpa16(bd + (row * BNNP + seg * 4) * 4,
                  B + (size_t)(kc * BK32 + row) * ldb + seg * 4);
        }
    }
    asm volatile("cp.async.commit_group;" ::: "memory");
}

__device__ __forceinline__ void compute_chunk_nn(
    const float* __restrict__ As, const float* __restrict__ Bs,
    float (&acc)[4][4][4], int wm, int wn, int gr, int kc)
{
    const int slot4 = (kc ^ (gr & 3)) * 4;
    uint32_t a[2][4][4], b[2][4][2];
#pragma unroll
    for (int mt = 0; mt < 4; mt++) {
        int r0 = wm * 64 + mt * 16 + gr;
        float4 u = *(const float4*)(As + r0 * BK32 + slot4);
        float4 w = *(const float4*)(As + (r0 + 8) * BK32 + slot4);
        a[0][mt][0] = __float_as_uint(u.x); a[0][mt][1] = __float_as_uint(w.x);
        a[0][mt][2] = __float_as_uint(u.y); a[0][mt][3] = __float_as_uint(w.y);
        a[1][mt][0] = __float_as_uint(u.z); a[1][mt][1] = __float_as_uint(w.z);
        a[1][mt][2] = __float_as_uint(u.w); a[1][mt][3] = __float_as_uint(w.w);
    }
#pragma unroll
    for (int k8 = 0; k8 < 2; k8++)
#pragma unroll
        for (int nt = 0; nt < 4; nt++) {
            const float* p = Bs + (k8 * 8 + kc) * BNNP + wn * 32 + nt * 8 + gr;
            b[k8][nt][0] = __float_as_uint(p[0]);
            b[k8][nt][1] = __float_as_uint(p[4 * BNNP]);
        }
#pragma unroll
    for (int k8 = 0; k8 < 2; k8++)
#pragma unroll
        for (int mt = 0; mt < 4; mt++)
#pragma unroll
            for (int nt = 0; nt < 4; nt++)
                mma_tf32(acc[mt][nt], a[k8][mt], b[k8][nt]);
}

// ---------------- fused split: x/y/W -> bf16 [hi | lo] --------------------------
__global__ void split_all(const float* __restrict__ x, const float* __restrict__ y,
                          const float* __restrict__ Wq, const float* __restrict__ Wk,
                          const float* __restrict__ Wv)
{
    constexpr size_t NX = (size_t)Bb * Mm * Dd;
    constexpr size_t NY = (size_t)BSs * Mm * Dd;
    constexpr size_t NW = (size_t)Dd * Dd;
    size_t i = (size_t)blockIdx.x * blockDim.x + threadIdx.x;
    if (i < NX) {
        int r = (int)(i / Dd), c = (int)(i % Dd);
        float v = x[i];
        __nv_bfloat16 h = __float2bfloat16(v);
        g_x2[(size_t)r * 512 + c] = h;
        g_x2[(size_t)r * 512 + 256 + c] = __float2bfloat16(v - __bfloat162float(h));
    } else if (i < NX + NY) {
        size_t e = i - NX;
        int r = (int)(e / Dd), c = (int)(e % Dd);
        float v = y[e];
        __nv_bfloat16 h = __float2bfloat16(v);
        g_y2[(size_t)r * 512 + c] = h;
        g_y2[(size_t)r * 512 + 256 + c] = __float2bfloat16(v - __bfloat162float(h));
    } else if (i < NX + NY + 3 * NW) {
        size_t j = i - NX - NY;
        int w = (int)(j / NW);
        size_t e = j % NW;
        int r = (int)(e / Dd), c = (int)(e % Dd);
        const float* W = (w == 0) ? Wq : (w == 1) ? Wk : Wv;
        float v = W[e];
        __nv_bfloat16 h = __float2bfloat16(v);
        g_W2[w][(size_t)r * 512 + c] = h;
        g_W2[w][(size_t)r * 512 + 256 + c] = __float2bfloat16(v - __bfloat162float(h));
    }
}

// ---------------- projections (fused 3-term bf16) -------------------------------
__global__ __launch_bounds__(256, 2) void proj_kernel()
{
    int z = blockIdx.z;
    bool isY = z >= 3;
    if (isY && blockIdx.y >= 32) return;
    int mat = z % 3;
    const __nv_bfloat16* A2 = isY ? g_y2 : g_x2;
    const __nv_bfloat16* B2 = g_W2[mat];
    int row0 = blockIdx.y * 128, col0 = blockIdx.x * 128;

    BF16_SETUP();
    gemm_bf16(A2 + (size_t)row0 * 512, B2 + (size_t)col0 * 512,
              acc, sb, wm, wn, lane);

    if (mat < 2) {
        __nv_bfloat16* Q2 = (mat == 0) ? (isY ? g_Qy2 : g_Qx2) : (isY ? g_Ky2 : g_Kx2);
#pragma unroll
        for (int mt = 0; mt < 4; mt++) {
            int r = row0 + wm * 64 + mt * 16 + gr;
#pragma unroll
            for (int nt = 0; nt < 4; nt++) {
                int c = col0 + wn * 32 + nt * 8 + kc * 2;
#pragma unroll
                for (int h2 = 0; h2 < 2; h2++) {
                    int rr = r + h2 * 8;
                    float v0 = acc[mt][nt][h2 * 2], v1 = acc[mt][nt][h2 * 2 + 1];
                    __nv_bfloat16 h0 = __float2bfloat16(v0);
                    __nv_bfloat16 h1 = __float2bfloat16(v1);
                    __nv_bfloat162 hi; hi.x = h0; hi.y = h1;
                    __nv_bfloat162 lo;
                    lo.x = __float2bfloat16(v0 - __bfloat162float(h0));
                    lo.y = __float2bfloat16(v1 - __bfloat162float(h1));
                    *(__nv_bfloat162*)(Q2 + (size_t)rr * 512 + c) = hi;
                    *(__nv_bfloat162*)(Q2 + (size_t)rr * 512 + 256 + c) = lo;
                }
            }
        }
    } else {
        float* V = isY ? g_Vy : g_Vx;
#pragma unroll
        for (int mt = 0; mt < 4; mt++) {
            int r = row0 + wm * 64 + mt * 16 + gr;
#pragma unroll
            for (int nt = 0; nt < 4; nt++) {
                int c = col0 + wn * 32 + nt * 8 + kc * 2;
#pragma unroll
                for (int h2 = 0; h2 < 2; h2++) {
                    int rr = r + h2 * 8;
                    *(float2*)(V + (size_t)rr * Dd + c) =
                        make_float2(tf32_rna(acc[mt][nt][h2 * 2]),
                                    tf32_rna(acc[mt][nt][h2 * 2 + 1]));
                }
            }
        }
    }
}

// ---------------- masked score GEMMs (fused 3-term bf16) -------------------------
// MODE 2 additionally writes the float mask_xy output (identical indexing).
template<int MODE>
__global__ __launch_bounds__(256, 2) void scores_kernel(float* __restrict__ outbase,
                                                        float* __restrict__ mxy)
{
    int zb = blockIdx.z;
    const __nv_bfloat16 *A, *Bp;
    const unsigned char *mr, *mc;
    float* C = outbase + (size_t)zb * Mm * Mm;
    float* Mx = (MODE == 2) ? (mxy + (size_t)zb * Mm * Mm) : nullptr;
    if (MODE == 0) {
        A = g_Qx2 + (size_t)zb * Mm * 512; Bp = g_Kx2 + (size_t)zb * Mm * 512;
        mr = g_mx + zb * Mm; mc = mr;
    } else if (MODE == 1) {
        A = g_Qy2 + (size_t)zb * Mm * 512; Bp = g_Ky2 + (size_t)zb * Mm * 512;
        mr = g_my + zb * Mm; mc = mr;
    } else {
        int n = zb >> 3, s = zb & 7, b = s * 8 + n;
        A = g_Qx2 + (size_t)b * Mm * 512; Bp = g_Ky2 + (size_t)s * Mm * 512;
        mr = g_mx + b * Mm; mc = g_my + s * Mm;
    }
    int row0 = blockIdx.y * 128, col0 = blockIdx.x * 128;

    BF16_SETUP();
    gemm_bf16(A + (size_t)row0 * 512, Bp + (size_t)col0 * 512,
              acc, sb, wm, wn, lane);

#pragma unroll
    for (int mt = 0; mt < 4; mt++) {
        int r = row0 + wm * 64 + mt * 16 + gr;
        bool rm0 = mr[r] != 0, rm1 = mr[r + 8] != 0;
#pragma unroll
        for (int nt = 0; nt < 4; nt++) {
            int c = col0 + wn * 32 + nt * 8 + kc * 2;
            bool c0 = mc[c] != 0, c1 = mc[c + 1] != 0;
            bool m00 = rm0 && c0, m01 = rm0 && c1;
            bool m10 = rm1 && c0, m11 = rm1 && c1;
            float2 v0, v1;
            v0.x = m00 ? acc[mt][nt][0] : NEG_FILL_F;
            v0.y = m01 ? acc[mt][nt][1] : NEG_FILL_F;
            v1.x = m10 ? acc[mt][nt][2] : NEG_FILL_F;
            v1.y = m11 ? acc[mt][nt][3] : NEG_FILL_F;
            *(float2*)(C + (size_t)r * Mm + c) = v0;
            *(float2*)(C + (size_t)(r + 8) * Mm + c) = v1;
            if (MODE == 2) {
                *(float2*)(Mx + (size_t)r * Mm + c) =
                    make_float2(m00 ? 1.f : 0.f, m01 ? 1.f : 0.f);
                *(float2*)(Mx + (size_t)(r + 8) * Mm + c) =
                    make_float2(m10 ? 1.f : 0.f, m11 ? 1.f : 0.f);
            }
        }
    }
}

// ---------------- context GEMMs: ctx = P @ V (NN, 1-pass tf32) -------------------
__global__ __launch_bounds__(256, 2) void ctx_kernel(float* __restrict__ out, int which)
{
    extern __shared__ char smemc[];
    float* As = (float*)smemc;
    float* Bs = As + DEPTH_NN * ASTG32;
    int b = blockIdx.z;
    const float* P = (which ? g_Py : g_Px) + (size_t)b * Mm * Mm;
    const float* V = (which ? g_Vy : g_Vx) + (size_t)b * Mm * Dd;
    int row0 = blockIdx.y * 128, col0 = blockIdx.x * 128;

    int wid = threadIdx.x >> 5, lane = threadIdx.x & 31;
    int wm = wid >> 2, wn = wid & 3;
    int gr = lane >> 2, kc = lane & 3;
    float acc[4][4][4];
#pragma unroll
    for (int i = 0; i < 4; i++)
#pragma unroll
        for (int j = 0; j < 4; j++)
#pragma unroll
            for (int q = 0; q < 4; q++) acc[i][j][q] = 0.f;

    const float* Ap = P + (size_t)row0 * Mm;
    const float* Bp = V + col0;
    uint32_t asb = smem_u32(As), bsb = smem_u32(Bs);
    constexpr int nch = Mm / BK32;   // 32
#pragma unroll
    for (int s = 0; s < DEPTH_NN - 1; s++)
        issue_stage_nn(Ap, Mm, Bp, Dd, s, nch, asb, bsb);
    for (int c = 0; c < nch; c++) {
        asm volatile("cp.async.wait_group 2;" ::: "memory");
        __syncthreads();
        issue_stage_nn(Ap, Mm, Bp, Dd, c + DEPTH_NN - 1, nch, asb, bsb);
        int buf = c & (DEPTH_NN - 1);
        compute_chunk_nn(As + buf * ASTG32, Bs + buf * BSTG_NN, acc, wm, wn, gr, kc);
    }

    float* O = out + (size_t)b * Mm * Dd;
#pragma unroll
    for (int mt = 0; mt < 4; mt++) {
        int r = row0 + wm * 64 + mt * 16 + gr;
#pragma unroll
        for (int nt = 0; nt < 4; nt++) {
            int c = col0 + wn * 32 + nt * 8 + kc * 2;
            *(float2*)(O + (size_t)r * Dd + c) =
                make_float2(acc[mt][nt][0], acc[mt][nt][1]);
            *(float2*)(O + (size_t)(r + 8) * Dd + c) =
                make_float2(acc[mt][nt][2], acc[mt][nt][3]);
        }
    }
}

// ---------------- mask normalization (dtype-agnostic) ----------------------------
__global__ void norm_masks_kernel(const unsigned int* __restrict__ mx_in,
                                  const unsigned int* __restrict__ my_in)
{
    const unsigned int* in = (blockIdx.x == 0) ? mx_in : my_in;
    unsigned char* out = (blockIdx.x == 0) ? g_mx : g_my;
    int n = (blockIdx.x == 0) ? Bb * Mm : BSs * Mm;

    __shared__ int s_flag;
    if (threadIdx.x == 0) s_flag = 0;
    __syncthreads();
    int local = 0;
    for (int i = threadIdx.x; i < n / 4; i += blockDim.x)
        if (in[i] > 1u) local = 1;
    if (local) atomicOr(&s_flag, 1);
    __syncthreads();
    bool byte_packed = (s_flag != 0);

    const unsigned char* inb = (const unsigned char*)in;
    for (int i = threadIdx.x; i < n; i += blockDim.x)
        out[i] = byte_packed ? (inb[i] != 0 ? 1 : 0) : (in[i] != 0u ? 1 : 0);
}

// ---------------- row softmax (512 wide) ------------------------------------------
// mode 0/1: tf32-rna probs, sp-permuted, to g_Px/g_Py. mode 2: raw fp32 in place.
__global__ __launch_bounds__(256) void softmax_kernel(
    const float* __restrict__ in, float* __restrict__ outp, int mode)
{
    float* outbase = (mode == 0) ? g_Px : (mode == 1) ? g_Py : outp;
    size_t row = blockIdx.x;
    const float* p = in + row * Mm;
    float* o = outbase + row * Mm;
    int t = threadIdx.x;

    float v0 = p[t];
    float v1 = p[t + 256];
    float m = fmaxf(v0, v1);
#pragma unroll
    for (int off = 16; off; off >>= 1)
        m = fmaxf(m, __shfl_xor_sync(0xffffffffu, m, off));
    __shared__ float smax[8], ssum[8];
    if ((t & 31) == 0) smax[t >> 5] = m;
    __syncthreads();
    float bm = smax[0];
#pragma unroll
    for (int i = 1; i < 8; i++) bm = fmaxf(bm, smax[i]);

    float e0 = __expf(v0 - bm);
    float e1 = __expf(v1 - bm);
    float s = e0 + e1;
#pragma unroll
    for (int off = 16; off; off >>= 1)
        s += __shfl_xor_sync(0xffffffffu, s, off);
    if ((t & 31) == 0) ssum[t >> 5] = s;
    __syncthreads();
    float tot = 0.f;
#pragma unroll
    for (int i = 0; i < 8; i++) tot += ssum[i];
    float inv = 1.0f / tot;
    if (mode < 2) {
        o[sp(t)] = tf32_rna(e0 * inv);
        o[sp(t + 256)] = tf32_rna(e1 * inv);
    } else {
        o[t] = e0 * inv;
        o[t + 256] = e1 * inv;
    }
}

// ---------------- y_len -------------------------------------------------------------
__global__ void ylen_kernel(float* __restrict__ out)
{
    int t = threadIdx.x;
    if (t >= 64) return;
    int s = t & 7;
    int sum = 0;
    for (int j = 0; j < Mm; j++) sum += g_my[s * Mm + j] ? 1 : 0;
    out[t] = (float)sum;
}

// ---------------- launch --------------------------------------------------------------
extern "C" void kernel_launch(void* const* d_in, const int* in_sizes, int n_in,
                              void* d_out, int out_size)
{
    const float* x  = (const float*)d_in[0];
    const float* y  = (const float*)d_in[1];
    const unsigned int* mask_x = (const unsigned int*)d_in[2];
    const unsigned int* mask_y = (const unsigned int*)d_in[3];
    const float* Wq = (const float*)d_in[4];
    const float* Wk = (const float*)d_in[5];
    const float* Wv = (const float*)d_in[6];

    float* out = (float*)d_out;
    float* out_ctx_x = out;                    // 64*512*256
    float* out_ctx_y = out + 8388608;          // 8*512*256
    float* out_sx    = out + 9437184;          // 64*512*512
    float* out_sy    = out + 26214400;         // 8*512*512
    float* out_pxy   = out + 28311552;         // 64*512*512
    float* out_mxy   = out + 45088768;         // 64*512*512
    float* out_ylen  = out + 61865984;         // 64

    cudaFuncSetAttribute(proj_kernel, cudaFuncAttributeMaxDynamicSharedMemorySize, DSMEM_BF);
    cudaFuncSetAttribute(scores_kernel<0>, cudaFuncAttributeMaxDynamicSharedMemorySize, DSMEM_BF);
    cudaFuncSetAttribute(scores_kernel<1>, cudaFuncAttributeMaxDynamicSharedMemorySize, DSMEM_BF);
    cudaFuncSetAttribute(scores_kernel<2>, cudaFuncAttributeMaxDynamicSharedMemorySize, DSMEM_BF);
    cudaFuncSetAttribute(ctx_kernel, cudaFuncAttributeMaxDynamicSharedMemorySize, DSMEM_NN);

    dim3 blk(256);

    norm_masks_kernel<<<2, 1024>>>(mask_x, mask_y);                          // 1
    {
        constexpr size_t TOT = (size_t)Bb * Mm * Dd + (size_t)BSs * Mm * Dd
                             + 3 * (size_t)Dd * Dd;
        split_all<<<(unsigned)((TOT + 255) / 256), 256>>>(x, y, Wq, Wk, Wv);  // 2
    }
    proj_kernel<<<dim3(2, 256, 6), blk, DSMEM_BF>>>();                       // 3
    scores_kernel<0><<<dim3(4, 4, 64), blk, DSMEM_BF>>>(out_sx, nullptr);    // 4 <- profiled
    scores_kernel<2><<<dim3(4, 4, 64), blk, DSMEM_BF>>>(out_pxy, out_mxy);   // 5
    scores_kernel<1><<<dim3(4, 4, 8),  blk, DSMEM_BF>>>(out_sy, nullptr);    // 6

    softmax_kernel<<<Bb * Mm, 256>>>(out_sx, nullptr, 0);
    softmax_kernel<<<BSs * Mm, 256>>>(out_sy, nullptr, 1);
    softmax_kernel<<<Bb * Mm, 256>>>(out_pxy, out_pxy, 2);

    ctx_kernel<<<dim3(2, 4, 64), blk, DSMEM_NN>>>(out_ctx_x, 0);
    ctx_kernel<<<dim3(2, 4, 8),  blk, DSMEM_NN>>>(out_ctx_y, 1);

    ylen_kernel<<<1, 64>>>(out_ylen);
}